// round 15
// baseline (speedup 1.0000x reference)
#include <cuda_runtime.h>
#include <cstdint>

// ---------------- problem constants ----------------
#define T_LEN 4096
#define D_DIM 2048
#define H_N   6
#define DKDIM 256
#define DVDIM 512
#define KD    1536   // H_N*DKDIM
#define VD    3072   // H_N*DVDIM
#define GENW  256
#define KSZ   4

// ---------------- scratch (static device, allocation-free) ----------------
__device__ float g_q[(size_t)T_LEN*KD];
__device__ float g_k[(size_t)T_LEN*KD];
__device__ float g_x[(size_t)T_LEN*VD];      // x = h@Wv; later reused as y (permuted tf32)
__device__ float g_v[(size_t)T_LEN*VD];      // conv+silu output
__device__ float g_dyn1[(size_t)T_LEN*GENW];
__device__ float g_dyn[(size_t)T_LEN*4];
__device__ float g_gate[(size_t)T_LEN*VD];
__device__ float g_o[(size_t)T_LEN*VD];      // scan output
__device__ float g_eb[(size_t)T_LEN*H_N*2];  // {eg, beta} per (t,head)
__device__ float g_sc4[(size_t)(T_LEN/4)*H_N*28];  // per-4-step-group coefficients

// tf32-rounded, k-permuted GEMM operands (weights also transposed to [N,K])
__device__ float g_hr [(size_t)T_LEN*D_DIM];
__device__ float g_wqr[(size_t)KD*D_DIM];
__device__ float g_wkr[(size_t)KD*D_DIM];
__device__ float g_wvr[(size_t)VD*D_DIM];
__device__ float g_wgr[(size_t)VD*D_DIM];
__device__ float g_g1r[(size_t)GENW*D_DIM];
__device__ float g_wor[(size_t)D_DIM*VD];

__device__ __forceinline__ float siluf(float x) { return x / (1.0f + expf(-x)); }

__device__ __forceinline__ float f2tf32f(float x) {
    uint32_t u;
    asm("cvt.rna.tf32.f32 %0, %1;" : "=r"(u) : "f"(x));
    return __uint_as_float(u);
}
__device__ __forceinline__ uint32_t smem_u32(const void* p) {
    uint32_t a;
    asm("{ .reg .u64 t; cvta.to.shared.u64 t, %1; cvt.u32.u64 %0, t; }" : "=r"(a) : "l"(p));
    return a;
}
__device__ __forceinline__ void cp16s(uint32_t sa, const void* g) {
    asm volatile("cp.async.cg.shared.global [%0], [%1], 16;" :: "r"(sa), "l"(g) : "memory");
}

// ---------------- prep: tf32 round + k-permute (+ weight transpose) ----------------
__global__ __launch_bounds__(256)
void prep_kernel(const float* __restrict__ h,
                 const float* __restrict__ wq, const float* __restrict__ wk,
                 const float* __restrict__ wv, const float* __restrict__ wg,
                 const float* __restrict__ g1, const float* __restrict__ wo,
                 float* __restrict__ hr,
                 float* __restrict__ wqr, float* __restrict__ wkr,
                 float* __restrict__ wvr, float* __restrict__ wgr,
                 float* __restrict__ g1r, float* __restrict__ wor) {
    int b = blockIdx.x;
    if (b < 2048) {
        size_t e0 = ((size_t)b * 256 + threadIdx.x) * 16;
        float4 r0 = *(const float4*)(h + e0);
        float4 r1 = *(const float4*)(h + e0 + 4);
        float4 r2 = *(const float4*)(h + e0 + 8);
        float4 r3 = *(const float4*)(h + e0 + 12);
        float4 o0 = make_float4(f2tf32f(r0.x), f2tf32f(r1.x), f2tf32f(r2.x), f2tf32f(r3.x));
        float4 o1 = make_float4(f2tf32f(r0.y), f2tf32f(r1.y), f2tf32f(r2.y), f2tf32f(r3.y));
        float4 o2 = make_float4(f2tf32f(r0.z), f2tf32f(r1.z), f2tf32f(r2.z), f2tf32f(r3.z));
        float4 o3 = make_float4(f2tf32f(r0.w), f2tf32f(r1.w), f2tf32f(r2.w), f2tf32f(r3.w));
        *(float4*)(hr + e0)      = o0;
        *(float4*)(hr + e0 + 4)  = o1;
        *(float4*)(hr + e0 + 8)  = o2;
        *(float4*)(hr + e0 + 12) = o3;
        return;
    }
    b -= 2048;
    const float* W; float* O; int K, N;
    if (b < 768)                 { W = wq; O = wqr; K = D_DIM; N = KD; }
    else if ((b -= 768) < 768)   { W = wk; O = wkr; K = D_DIM; N = KD; }
    else if ((b -= 768) < 1536)  { W = wv; O = wvr; K = D_DIM; N = VD; }
    else if ((b -= 1536) < 1536) { W = wg; O = wgr; K = D_DIM; N = VD; }
    else if ((b -= 1536) < 128)  { W = g1; O = g1r; K = D_DIM; N = GENW; }
    else                         { b -= 128; W = wo; O = wor; K = VD; N = D_DIM; }
    int ntx = N >> 6;
    int tn = b % ntx, tk = b / ntx;
    int kb = tk * 64, nb = tn * 64;
    __shared__ float tile[64][65];
    int c = threadIdx.x & 63, r0i = threadIdx.x >> 6;
    #pragma unroll
    for (int i = 0; i < 16; i++) {
        int r = r0i + i * 4;
        tile[r][c] = W[(size_t)(kb + r) * N + nb + c];
    }
    __syncthreads();
    int nl = threadIdx.x >> 2, grp = threadIdx.x & 3;
    float* orow = O + (size_t)(nb + nl) * K + kb + grp * 16;
    #pragma unroll
    for (int a = 0; a < 4; a++) {
        float4 o;
        o.x = f2tf32f(tile[grp*16 + a     ][nl]);
        o.y = f2tf32f(tile[grp*16 + a + 4 ][nl]);
        o.z = f2tf32f(tile[grp*16 + a + 8 ][nl]);
        o.w = f2tf32f(tile[grp*16 + a + 12][nl]);
        *(float4*)(orow + a * 4) = o;
    }
}

// ---------------- tf32 GEMM body (permuted operands, LDS.128 frags) ----------------
#define GEMM_SMEM 65536

__device__ __forceinline__ void gemm_body(
    const float* __restrict__ A, const float* __restrict__ B, float* __restrict__ C,
    int K, int Ns, int row0, int col0, int act)
{
    extern __shared__ float sm[];
    const int tid  = threadIdx.x;
    const int warp = tid >> 5, lane = tid & 31;
    const int gid  = lane >> 2, tig = lane & 3;
    const int wm   = warp >> 1, wn = warp & 1;
    const int KT   = K >> 4;
    const uint32_t smb = smem_u32(sm);

    float acc[2][8][4];
    #pragma unroll
    for (int i = 0; i < 2; i++)
        #pragma unroll
        for (int j = 0; j < 8; j++)
            #pragma unroll
            for (int cc = 0; cc < 4; cc++) acc[i][j][cc] = 0.0f;

    const int rA = tid >> 2,        cA = (tid & 3) * 4;
    const float* Abase = A + (size_t)(row0 + rA) * K + cA;
    const float* Bbase = B + (size_t)(col0 + rA) * K + cA;

    auto issue = [&](int kt) {
        if (kt < KT) {
            uint32_t so = smb + (uint32_t)(kt & 3) * 16384u + (uint32_t)(rA * 16 + cA) * 4u;
            int k0 = kt << 4;
            cp16s(so,                 Abase + k0);
            cp16s(so + 4096,          Abase + k0 + (size_t)64 * K);
            cp16s(so + 8192,          Bbase + k0);
            cp16s(so + 8192 + 4096,   Bbase + k0 + (size_t)64 * K);
        }
        asm volatile("cp.async.commit_group;" ::: "memory");
    };

    issue(0); issue(1); issue(2);
    for (int kt = 0; kt < KT; ++kt) {
        asm volatile("cp.async.wait_group 2;" ::: "memory");
        __syncthreads();
        issue(kt + 3);

        const float* As = sm + (kt & 3) * 4096;
        const float* Bs = As + 2048;

        float4 A0[2], A1[2];
        #pragma unroll
        for (int i = 0; i < 2; i++) {
            int m = wm * 32 + i * 16 + gid;
            A0[i] = *(const float4*)(As + m * 16 + tig * 4);
            A1[i] = *(const float4*)(As + (m + 8) * 16 + tig * 4);
        }
        #pragma unroll
        for (int jh = 0; jh < 2; jh++) {
            float4 Bv[4];
            #pragma unroll
            for (int j = 0; j < 4; j++) {
                int n = wn * 64 + (jh * 4 + j) * 8 + gid;
                Bv[j] = *(const float4*)(Bs + n * 16 + tig * 4);
            }
            #pragma unroll
            for (int i = 0; i < 2; i++)
                #pragma unroll
                for (int j = 0; j < 4; j++) {
                    float* ac = acc[i][jh * 4 + j];
                    asm volatile(
                        "mma.sync.aligned.m16n8k8.row.col.f32.tf32.tf32.f32 "
                        "{%0,%1,%2,%3}, {%4,%5,%6,%7}, {%8,%9}, {%0,%1,%2,%3};"
                        : "+f"(ac[0]), "+f"(ac[1]), "+f"(ac[2]), "+f"(ac[3])
                        : "r"(__float_as_uint(A0[i].x)), "r"(__float_as_uint(A1[i].x)),
                          "r"(__float_as_uint(A0[i].y)), "r"(__float_as_uint(A1[i].y)),
                          "r"(__float_as_uint(Bv[j].x)), "r"(__float_as_uint(Bv[j].y)));
                    asm volatile(
                        "mma.sync.aligned.m16n8k8.row.col.f32.tf32.tf32.f32 "
                        "{%0,%1,%2,%3}, {%4,%5,%6,%7}, {%8,%9}, {%0,%1,%2,%3};"
                        : "+f"(ac[0]), "+f"(ac[1]), "+f"(ac[2]), "+f"(ac[3])
                        : "r"(__float_as_uint(A0[i].z)), "r"(__float_as_uint(A1[i].z)),
                          "r"(__float_as_uint(A0[i].w)), "r"(__float_as_uint(A1[i].w)),
                          "r"(__float_as_uint(Bv[j].z)), "r"(__float_as_uint(Bv[j].w)));
                }
        }
    }

    #pragma unroll
    for (int i = 0; i < 2; ++i) {
        int row = row0 + wm * 32 + i * 16 + gid;
        #pragma unroll
        for (int j = 0; j < 8; ++j) {
            int col = col0 + wn * 64 + j * 8 + 2 * tig;
            float v0 = acc[i][j][0], v1 = acc[i][j][1];
            float v2 = acc[i][j][2], v3 = acc[i][j][3];
            if (act) { v0 = siluf(v0); v1 = siluf(v1); v2 = siluf(v2); v3 = siluf(v3); }
            *(float2*)(C + (size_t)row * Ns + col)       = make_float2(v0, v1);
            *(float2*)(C + (size_t)(row + 8) * Ns + col) = make_float2(v2, v3);
        }
    }
}

__global__ __launch_bounds__(256, 2)
void proj_gemm_kernel(const float* __restrict__ hR,
                      const float* __restrict__ WqR, const float* __restrict__ WkR,
                      const float* __restrict__ WvR, const float* __restrict__ WgR,
                      const float* __restrict__ g1R,
                      float* __restrict__ q, float* __restrict__ k,
                      float* __restrict__ x, float* __restrict__ g,
                      float* __restrict__ d1) {
    const int by = blockIdx.y;
    const float* B; float* C; int Ns, col0, act;
    if (by < 12)      { B = WqR; C = q;  Ns = KD;   col0 = by * 128;        act = 1; }
    else if (by < 24) { B = WkR; C = k;  Ns = KD;   col0 = (by - 12) * 128; act = 1; }
    else if (by < 48) { B = WvR; C = x;  Ns = VD;   col0 = (by - 24) * 128; act = 0; }
    else if (by < 72) { B = WgR; C = g;  Ns = VD;   col0 = (by - 48) * 128; act = 0; }
    else              { B = g1R; C = d1; Ns = GENW; col0 = (by - 72) * 128; act = 1; }
    gemm_body(hR, B, C, D_DIM, Ns, blockIdx.x * 128, col0, act);
}

__global__ __launch_bounds__(256, 2)
void wo_gemm_kernel(const float* __restrict__ yR, const float* __restrict__ WoR,
                    float* __restrict__ out) {
    gemm_body(yR, WoR, out, VD, D_DIM, blockIdx.x * 128, blockIdx.y * 128, 0);
}

// ---------------- dyn = dyn1[T,256] @ gen_w2[256,4] (warp per token) ----------------
__global__ __launch_bounds__(256)
void dyn2_kernel(const float* __restrict__ dyn1, const float* __restrict__ w2,
                 float* __restrict__ dyn) {
    int t    = blockIdx.x * 8 + (threadIdx.x >> 5);
    int lane = threadIdx.x & 31;
    const float* r = dyn1 + (size_t)t * GENW;
    float a0 = 0.f, a1 = 0.f, a2 = 0.f, a3 = 0.f;
    #pragma unroll
    for (int i = 0; i < 8; i++) {
        int d = lane + 32*i;
        float v = r[d];
        const float* w = w2 + d*4;
        a0 += v*w[0]; a1 += v*w[1]; a2 += v*w[2]; a3 += v*w[3];
    }
    #pragma unroll
    for (int off = 16; off; off >>= 1) {
        a0 += __shfl_xor_sync(0xffffffffu, a0, off);
        a1 += __shfl_xor_sync(0xffffffffu, a1, off);
        a2 += __shfl_xor_sync(0xffffffffu, a2, off);
        a3 += __shfl_xor_sync(0xffffffffu, a3, off);
    }
    if (lane == 0) {
        dyn[t*4+0] = a0; dyn[t*4+1] = a1; dyn[t*4+2] = a2; dyn[t*4+3] = a3;
    }
}

// ---------------- betag -> eb{e, beta} per (t,head) ----------------
__global__ __launch_bounds__(256)
void betag_kernel(const float* __restrict__ h, const float* __restrict__ Wb,
                  const float* __restrict__ Wa, const float* __restrict__ A_log,
                  const float* __restrict__ dt_bias, float* __restrict__ eb) {
    int t = blockIdx.x;
    const float* hr = h + (size_t)t * D_DIM;
    float acc[12];
    #pragma unroll
    for (int j = 0; j < 12; j++) acc[j] = 0.f;
    for (int d = threadIdx.x; d < D_DIM; d += 256) {
        float hv = hr[d];
        const float* wb = Wb + d*6;
        const float* wa = Wa + d*6;
        #pragma unroll
        for (int j = 0; j < 6; j++) {
            acc[j]   += hv * wb[j];
            acc[6+j] += hv * wa[j];
        }
    }
    #pragma unroll
    for (int j = 0; j < 12; j++)
        #pragma unroll
        for (int off = 16; off; off >>= 1)
            acc[j] += __shfl_xor_sync(0xffffffffu, acc[j], off);

    __shared__ float red[8][12];
    int w = threadIdx.x >> 5, lane = threadIdx.x & 31;
    if (lane == 0) {
        #pragma unroll
        for (int j = 0; j < 12; j++) red[w][j] = acc[j];
    }
    __syncthreads();
    if (threadIdx.x < 12) {
        float s = 0.f;
        #pragma unroll
        for (int i = 0; i < 8; i++) s += red[i][threadIdx.x];
        int j = threadIdx.x;
        if (j < 6) {
            eb[(size_t)(t*6 + j) * 2 + 1] = 1.0f / (1.0f + expf(-s));     // beta
        } else {
            int hh = j - 6;
            float xx = s + dt_bias[hh];
            float sp = (xx > 20.0f) ? xx : log1pf(expf(xx));
            eb[(size_t)(t*6 + hh) * 2 + 0] = expf(-expf(A_log[hh]) * sp); // eg
        }
    }
}

// ---------------- dynamic short conv + silu ----------------
__global__ __launch_bounds__(256)
void conv_silu_kernel(const float* __restrict__ x, const float* __restrict__ dyn,
                      const float* __restrict__ cw, float* __restrict__ v) {
    int idx = blockIdx.x * 256 + threadIdx.x;
    int t = idx / (VD/4);
    if (t >= T_LEN) return;
    int c = (idx - t * (VD/4)) * 4;
    float d[4];
    #pragma unroll
    for (int j = 0; j < 4; j++) d[j] = dyn[t*4 + j];
    float a0 = 0.f, a1 = 0.f, a2 = 0.f, a3 = 0.f;
    #pragma unroll
    for (int j = 0; j < 4; j++) {
        int tt = t + j - 3;
        if (tt >= 0) {
            float4 xv = *(const float4*)(x + (size_t)tt * VD + c);
            a0 += (cw[(c+0)*4 + j] + d[j]) * xv.x;
            a1 += (cw[(c+1)*4 + j] + d[j]) * xv.y;
            a2 += (cw[(c+2)*4 + j] + d[j]) * xv.z;
            a3 += (cw[(c+3)*4 + j] + d[j]) * xv.w;
        }
    }
    float4 r;
    r.x = siluf(a0); r.y = siluf(a1); r.z = siluf(a2); r.w = siluf(a3);
    *(float4*)(v + (size_t)t * VD + c) = r;
}

// ---------------- l2norm(q,k) in place (warp per (t,h)) ----------------
__global__ __launch_bounds__(256)
void l2qk_kernel(float* __restrict__ q, float* __restrict__ k) {
    int vec  = blockIdx.x * 8 + (threadIdx.x >> 5);   // t*6 + h
    int lane = threadIdx.x & 31;
    float* qr = q + (size_t)vec * DKDIM;
    float* kr = k + (size_t)vec * DKDIM;
    float xq[8], xk[8];
    float sq = 0.f, sk = 0.f;
    #pragma unroll
    for (int i = 0; i < 8; i++) {
        xq[i] = qr[lane + 32*i]; xk[i] = kr[lane + 32*i];
        sq += xq[i]*xq[i]; sk += xk[i]*xk[i];
    }
    #pragma unroll
    for (int off = 16; off; off >>= 1) {
        sq += __shfl_xor_sync(0xffffffffu, sq, off);
        sk += __shfl_xor_sync(0xffffffffu, sk, off);
    }
    float rq = rsqrtf(sq + 1e-6f) * 0.0625f;   // fold DK^-0.5 into q
    float rk = rsqrtf(sk + 1e-6f);
    #pragma unroll
    for (int i = 0; i < 8; i++) {
        qr[lane + 32*i] = xq[i] * rq;
        kr[lane + 32*i] = xk[i] * rk;
    }
}

// ---------------- cross4: per 4-step group coefficients -> 28 floats ----------------
// Record layout (base ((t/4)*6 + head)*28):
// [0..3]  E0, E01, E012, E0123                       (decay prefix products)
// [4..7]  beta0..beta3
// [8..13] a10,a20,a21,a30,a31,a32   (a_ji = decay * (k_j.k_i))
// [14..17] qk0..qk3                 (q_i.k_i)
// [18..23] b10,b20,b21,b30,b31,b32  (b_ji = decay * (q_j.k_i))
// [24..26] w0=e1e2e3, w1=e2e3, w2=e3
__global__ __launch_bounds__(256)
void cross4_kernel(const float* __restrict__ q, const float* __restrict__ k,
                   const float* __restrict__ eb, float* __restrict__ sc) {
    int wg   = blockIdx.x * 8 + (threadIdx.x >> 5);   // 0..6143 = grp*6 + head
    int lane = threadIdx.x & 31;
    int grp  = wg / 6, head = wg - grp * 6;
    int t = grp * 4;

    float kv[4][8], qv[4][8];
    #pragma unroll
    for (int j = 0; j < 4; j++) {
        const float* kr = k + ((size_t)(t + j) * 6 + head) * DKDIM + lane;
        const float* qr = q + ((size_t)(t + j) * 6 + head) * DKDIM + lane;
        #pragma unroll
        for (int i = 0; i < 8; i++) { kv[j][i] = kr[32*i]; qv[j][i] = qr[32*i]; }
    }

    // 16 dot products
    float dt[16];
    #pragma unroll
    for (int z = 0; z < 16; z++) dt[z] = 0.f;
    #pragma unroll
    for (int i = 0; i < 8; i++) {
        dt[0]  += kv[1][i]*kv[0][i];   // kk10
        dt[1]  += kv[2][i]*kv[0][i];   // kk20
        dt[2]  += kv[2][i]*kv[1][i];   // kk21
        dt[3]  += kv[3][i]*kv[0][i];   // kk30
        dt[4]  += kv[3][i]*kv[1][i];   // kk31
        dt[5]  += kv[3][i]*kv[2][i];   // kk32
        dt[6]  += qv[1][i]*kv[0][i];   // qx10
        dt[7]  += qv[2][i]*kv[0][i];   // qx20
        dt[8]  += qv[2][i]*kv[1][i];   // qx21
        dt[9]  += qv[3][i]*kv[0][i];   // qx30
        dt[10] += qv[3][i]*kv[1][i];   // qx31
        dt[11] += qv[3][i]*kv[2][i];   // qx32
        dt[12] += qv[0][i]*kv[0][i];   // qk0
        dt[13] += qv[1][i]*kv[1][i];   // qk1
        dt[14] += qv[2][i]*kv[2][i];   // qk2
        dt[15] += qv[3][i]*kv[3][i];   // qk3
    }
    #pragma unroll
    for (int z = 0; z < 16; z++)
        #pragma unroll
        for (int off = 16; off; off >>= 1)
            dt[z] += __shfl_xor_sync(0xffffffffu, dt[z], off);

    if (lane == 0) {
        float e0 = eb[(size_t)((t+0)*6 + head)*2], b0 = eb[(size_t)((t+0)*6 + head)*2 + 1];
        float e1 = eb[(size_t)((t+1)*6 + head)*2], b1 = eb[(size_t)((t+1)*6 + head)*2 + 1];
        float e2 = eb[(size_t)((t+2)*6 + head)*2], b2 = eb[(size_t)((t+2)*6 + head)*2 + 1];
        float e3 = eb[(size_t)((t+3)*6 + head)*2], b3 = eb[(size_t)((t+3)*6 + head)*2 + 1];
        float E0 = e0, E01 = e0*e1, E012 = E01*e2, E0123 = E012*e3;
        float w2c = e3, w1c = e2*e3, w0c = e1*w1c;
        float* r = sc + (size_t)wg * 28;
        r[0]=E0; r[1]=E01; r[2]=E012; r[3]=E0123;
        r[4]=b0; r[5]=b1; r[6]=b2; r[7]=b3;
        r[8]  = e1*dt[0];   r[9]  = e1*e2*dt[1];  r[10] = e2*dt[2];
        r[11] = w0c*dt[3];  r[12] = w1c*dt[4];    r[13] = e3*dt[5];
        r[14]=dt[12]; r[15]=dt[13]; r[16]=dt[14]; r[17]=dt[15];
        r[18] = e1*dt[6];   r[19] = e1*e2*dt[7];  r[20] = e2*dt[8];
        r[21] = w0c*dt[9];  r[22] = w1c*dt[10];   r[23] = e3*dt[11];
        r[24]=w0c; r[25]=w1c; r[26]=w2c; r[27]=0.f;
    }
}

// ---------------- 4-step fused gated delta-rule scan: 2 cols/warp ----------------
// 384 blocks x 4 warps (proven optimum); scalar stride-32 loads (proven optimal).
// ONE 16-value butterfly per 4 steps. Inter-step coupling via precomputed scalars.
__global__ __launch_bounds__(128)
void scan_kernel(const float* __restrict__ q, const float* __restrict__ k,
                 const float* __restrict__ v, const float* __restrict__ sc4,
                 float* __restrict__ o) {
    const int warpg = blockIdx.x * 4 + (threadIdx.x >> 5);
    const int c0    = warpg * 2;
    const int head  = c0 >> 9;
    const int lane  = threadIdx.x & 31;

    const float* qb = q + head * DKDIM + lane;
    const float* kb = k + head * DKDIM + lane;

    float s0[8], s1[8];
    #pragma unroll
    for (int i = 0; i < 8; i++) { s0[i] = 0.f; s1[i] = 0.f; }

    for (int t = 0; t < T_LEN; t += 4) {
        const float* r = sc4 + ((size_t)(t >> 2) * 6 + head) * 28;
        float4 cE = *(const float4*)(r);       // E0,E01,E012,E0123
        float4 cB = *(const float4*)(r + 4);   // betas
        float4 cA0 = *(const float4*)(r + 8);  // a10,a20,a21,a30
        float4 cA1 = *(const float4*)(r + 12); // a31,a32,qk0,qk1
        float4 cA2 = *(const float4*)(r + 16); // qk2,qk3,b10,b20
        float4 cA3 = *(const float4*)(r + 20); // b21,b30,b31,b32
        float4 cW  = *(const float4*)(r + 24); // w0,w1,w2,-

        size_t o0 = (size_t)t * KD, o1 = o0 + KD, o2 = o1 + KD, o3 = o2 + KD;
        float k0[8], k1_[8], k2_[8], k3_[8];
        float q0[8], q1_[8], q2_[8], q3_[8];
        #pragma unroll
        for (int i = 0; i < 8; i++) {
            k0[i]  = kb[o0 + 32*i];  q0[i]  = qb[o0 + 32*i];
            k1_[i] = kb[o1 + 32*i];  q1_[i] = qb[o1 + 32*i];
            k2_[i] = kb[o2 + 32*i];  q2_[i] = qb[o2 + 32*i];
            k3_[i] = kb[o3 + 32*i];  q3_[i] = qb[o3 + 32*i];
        }
        float2 v0 = *(const float2*)(v + (size_t)t * VD + c0);
        float2 v1 = *(const float2*)(v + (size_t)(t+1) * VD + c0);
        float2 v2 = *(const float2*)(v + (size_t)(t+2) * VD + c0);
        float2 v3 = *(const float2*)(v + (size_t)(t+3) * VD + c0);

        // 8 reductions x 2 columns over the pre-group state
        float rk0a=0,rk1a=0,rk2a=0,rk3a=0, rq0a=0,rq1a=0,rq2a=0,rq3a=0;
        float rk0b=0,rk1b=0,rk2b=0,rk3b=0, rq0b=0,rq1b=0,rq2b=0,rq3b=0;
        #pragma unroll
        for (int i = 0; i < 8; i++) {
            float t0 = s0[i], t1 = s1[i];
            rk0a += k0[i]*t0;  rk0b += k0[i]*t1;
            rk1a += k1_[i]*t0; rk1b += k1_[i]*t1;
            rk2a += k2_[i]*t0; rk2b += k2_[i]*t1;
            rk3a += k3_[i]*t0; rk3b += k3_[i]*t1;
            rq0a += q0[i]*t0;  rq0b += q0[i]*t1;
            rq1a += q1_[i]*t0; rq1b += q1_[i]*t1;
            rq2a += q2_[i]*t0; rq2b += q2_[i]*t1;
            rq3a += q3_[i]*t0; rq3b += q3_[i]*t1;
        }
        #pragma unroll
        for (int off = 16; off; off >>= 1) {
            rk0a += __shfl_xor_sync(0xffffffffu, rk0a, off);
            rk1a += __shfl_xor_sync(0xffffffffu, rk1a, off);
            rk2a += __shfl_xor_sync(0xffffffffu, rk2a, off);
            rk3a += __shfl_xor_sync(0xffffffffu, rk3a, off);
            rq0a += __shfl_xor_sync(0xffffffffu, rq0a, off);
            rq1a += __shfl_xor_sync(0xffffffffu, rq1a, off);
            rq2a += __shfl_xor_sync(0xffffffffu, rq2a, off);
            rq3a += __shfl_xor_sync(0xffffffffu, rq3a, off);
            rk0b += __shfl_xor_sync(0xffffffffu, rk0b, off);
            rk1b += __shfl_xor_sync(0xffffffffu, rk1b, off);
            rk2b += __shfl_xor_sync(0xffffffffu, rk2b, off);
            rk3b += __shfl_xor_sync(0xffffffffu, rk3b, off);
            rq0b += __shfl_xor_sync(0xffffffffu, rq0b, off);
            rq1b += __shfl_xor_sync(0xffffffffu, rq1b, off);
            rq2b += __shfl_xor_sync(0xffffffffu, rq2b, off);
            rq3b += __shfl_xor_sync(0xffffffffu, rq3b, off);
        }

        // column 0
        float dv0a = (v0.x - cE.x*rk0a) * cB.x;
        float dv1a = (v1.x - cE.y*rk1a - cA0.x*dv0a) * cB.y;
        float dv2a = (v2.x - cE.z*rk2a - cA0.y*dv0a - cA0.z*dv1a) * cB.z;
        float dv3a = (v3.x - cE.w*rk3a - cA0.w*dv0a - cA1.x*dv1a - cA1.y*dv2a) * cB.w;
        // column 1
        float dv0b = (v0.y - cE.x*rk0b) * cB.x;
        float dv1b = (v1.y - cE.y*rk1b - cA0.x*dv0b) * cB.y;
        float dv2b = (v2.y - cE.z*rk2b - cA0.y*dv0b - cA0.z*dv1b) * cB.z;
        float dv3b = (v3.y - cE.w*rk3b - cA0.w*dv0b - cA1.x*dv1b - cA1.y*dv2b) * cB.w;

        if (lane == 0) {
            *(float2*)(o + (size_t)t * VD + c0) = make_float2(
                cE.x*rq0a + cA1.z*dv0a,
                cE.x*rq0b + cA1.z*dv0b);
            *(float2*)(o + (size_t)(t+1) * VD + c0) = make_float2(
                cE.y*rq1a + cA2.z*dv0a + cA1.w*dv1a,
                cE.y*rq1b + cA2.z*dv0b + cA1.w*dv1b);
            *(float2*)(o + (size_t)(t+2) * VD + c0) = make_float2(
                cE.z*rq2a + cA2.w*dv0a + cA3.x*dv1a + cA2.x*dv2a,
                cE.z*rq2b + cA2.w*dv0b + cA3.x*dv1b + cA2.x*dv2b);
            *(float2*)(o + (size_t)(t+3) * VD + c0) = make_float2(
                cE.w*rq3a + cA3.y*dv0a + cA3.z*dv1a + cA3.w*dv2a + cA2.y*dv3a,
                cE.w*rq3b + cA3.y*dv0b + cA3.z*dv1b + cA3.w*dv2b + cA2.y*dv3b);
        }

        // state update: s = E0123*s + (w0*dv0)k0 + (w1*dv1)k1 + (w2*dv2)k2 + dv3*k3
        float c0a = cW.x*dv0a, c1a = cW.y*dv1a, c2a = cW.z*dv2a;
        float c0b = cW.x*dv0b, c1b = cW.y*dv1b, c2b = cW.z*dv2b;
        #pragma unroll
        for (int i = 0; i < 8; i++) {
            s0[i] = cE.w*s0[i] + c0a*k0[i] + c1a*k1_[i] + c2a*k2_[i] + dv3a*k3_[i];
            s1[i] = cE.w*s1[i] + c0b*k0[i] + c1b*k1_[i] + c2b*k2_[i] + dv3b*k3_[i];
        }
    }
}

// ---------------- gated RMSNorm -> tf32-rounded, k-permuted y ----------------
__global__ __launch_bounds__(128)
void rmsnorm_gate_kernel(const float* __restrict__ o, const float* __restrict__ gate,
                         const float* __restrict__ nw, float* __restrict__ y) {
    int row = blockIdx.x;                  // t*6 + h
    int tid = threadIdx.x;
    size_t base = (size_t)(row / 6) * VD + (size_t)(row % 6) * DVDIM;
    int g = tid >> 2, a = tid & 3;

    float ov[4], gv[4], nv[4];
    float ss = 0.f;
    #pragma unroll
    for (int i = 0; i < 4; i++) {
        int c = g * 16 + a + 4 * i;
        ov[i] = o[base + c];
        gv[i] = gate[base + c];
        nv[i] = nw[c];
        ss += ov[i] * ov[i];
    }
    #pragma unroll
    for (int off = 16; off; off >>= 1) ss += __shfl_xor_sync(0xffffffffu, ss, off);
    __shared__ float red[4];
    int w = tid >> 5, lane = tid & 31;
    if (lane == 0) red[w] = ss;
    __syncthreads();
    float tot = red[0] + red[1] + red[2] + red[3];
    float rms = rsqrtf(tot * (1.0f / (float)DVDIM) + 1e-5f);

    float4 r;
    r.x = f2tf32f(ov[0] * rms * nv[0] * siluf(gv[0]));
    r.y = f2tf32f(ov[1] * rms * nv[1] * siluf(gv[1]));
    r.z = f2tf32f(ov[2] * rms * nv[2] * siluf(gv[2]));
    r.w = f2tf32f(ov[3] * rms * nv[3] * siluf(gv[3]));
    *(float4*)(y + base + g * 16 + 4 * a) = r;
}

// ---------------- launch ----------------
extern "C" void kernel_launch(void* const* d_in, const int* in_sizes, int n_in,
                              void* d_out, int out_size) {
    const float* h       = (const float*)d_in[0];
    const float* Wq      = (const float*)d_in[1];
    const float* Wk      = (const float*)d_in[2];
    const float* Wv      = (const float*)d_in[3];
    const float* Wb      = (const float*)d_in[4];
    const float* Wa      = (const float*)d_in[5];
    const float* Wg      = (const float*)d_in[6];
    const float* Wo      = (const float*)d_in[7];
    const float* A_log   = (const float*)d_in[8];
    const float* dt_bias = (const float*)d_in[9];
    const float* conv_w  = (const float*)d_in[10];
    const float* gen_w1  = (const float*)d_in[11];
    const float* gen_w2  = (const float*)d_in[12];
    const float* norm_w  = (const float*)d_in[13];
    float* out = (float*)d_out;

    float *pq, *pk, *px, *pv, *pd1, *pd, *pgate, *po, *peb, *psc4;
    float *phr, *pwqr, *pwkr, *pwvr, *pwgr, *pg1r, *pwor;
    cudaGetSymbolAddress((void**)&pq,    g_q);
    cudaGetSymbolAddress((void**)&pk,    g_k);
    cudaGetSymbolAddress((void**)&px,    g_x);
    cudaGetSymbolAddress((void**)&pv,    g_v);
    cudaGetSymbolAddress((void**)&pd1,   g_dyn1);
    cudaGetSymbolAddress((void**)&pd,    g_dyn);
    cudaGetSymbolAddress((void**)&pgate, g_gate);
    cudaGetSymbolAddress((void**)&po,    g_o);
    cudaGetSymbolAddress((void**)&peb,   g_eb);
    cudaGetSymbolAddress((void**)&psc4,  g_sc4);
    cudaGetSymbolAddress((void**)&phr,   g_hr);
    cudaGetSymbolAddress((void**)&pwqr,  g_wqr);
    cudaGetSymbolAddress((void**)&pwkr,  g_wkr);
    cudaGetSymbolAddress((void**)&pwvr,  g_wvr);
    cudaGetSymbolAddress((void**)&pwgr,  g_wgr);
    cudaGetSymbolAddress((void**)&pg1r,  g_g1r);
    cudaGetSymbolAddress((void**)&pwor,  g_wor);

    cudaFuncSetAttribute(proj_gemm_kernel, cudaFuncAttributeMaxDynamicSharedMemorySize, GEMM_SMEM);
    cudaFuncSetAttribute(wo_gemm_kernel,   cudaFuncAttributeMaxDynamicSharedMemorySize, GEMM_SMEM);

    // (0) round + permute h, transpose + round + permute weights
    prep_kernel<<<8320, 256>>>(h, Wq, Wk, Wv, Wg, gen_w1, Wo,
                               phr, pwqr, pwkr, pwvr, pwgr, pg1r, pwor);

    // (1) fused projections q|k|x|gate|dyn1 (74 x 32 tiles)
    proj_gemm_kernel<<<dim3(T_LEN/128, 74), 256, GEMM_SMEM>>>(
        phr, pwqr, pwkr, pwvr, pwgr, pg1r, pq, pk, px, pgate, pd1);

    // (2..6) elementwise stages
    dyn2_kernel<<<T_LEN/8, 256>>>(pd1, gen_w2, pd);
    betag_kernel<<<T_LEN, 256>>>(h, Wb, Wa, A_log, dt_bias, peb);
    conv_silu_kernel<<<(T_LEN*(VD/4))/256, 256>>>(px, pd, conv_w, pv);
    l2qk_kernel<<<(T_LEN*H_N)/8, 256>>>(pq, pk);
    cross4_kernel<<<(T_LEN/4*H_N)/8, 256>>>(pq, pk, peb, psc4);

    // (7) 4-step fused scan
    scan_kernel<<<384, 128>>>(pq, pk, pv, psc4, po);

    // (8) gated RMSNorm -> permuted tf32 y (reuses g_x)
    rmsnorm_gate_kernel<<<T_LEN*H_N, 128>>>(po, pgate, norm_w, px);

    // (9) out = y @ Wo
    wo_gemm_kernel<<<dim3(T_LEN/128, D_DIM/128), 256, GEMM_SMEM>>>(px, pwor, out);
}

// round 16
// speedup vs baseline: 1.4730x; 1.4730x over previous
#include <cuda_runtime.h>
#include <cstdint>

// ---------------- problem constants ----------------
#define T_LEN 4096
#define D_DIM 2048
#define H_N   6
#define DKDIM 256
#define DVDIM 512
#define KD    1536   // H_N*DKDIM
#define VD    3072   // H_N*DVDIM
#define GENW  256
#define KSZ   4

// ---------------- scratch (static device, allocation-free) ----------------
__device__ float g_q[(size_t)T_LEN*KD];
__device__ float g_k[(size_t)T_LEN*KD];
__device__ float g_x[(size_t)T_LEN*VD];      // x = h@Wv; later reused as y (permuted tf32)
__device__ float g_v[(size_t)T_LEN*VD];      // conv+silu output
__device__ float g_dyn1[(size_t)T_LEN*GENW];
__device__ float g_dyn[(size_t)T_LEN*4];
__device__ float g_gate[(size_t)T_LEN*VD];
__device__ float g_o[(size_t)T_LEN*VD];      // scan output
__device__ float4 g_scal[(size_t)T_LEN*H_N]; // {eg, beta, qk, kk|qx} per (t,head)

// tf32-rounded, k-permuted GEMM operands (weights also transposed to [N,K])
__device__ float g_hr [(size_t)T_LEN*D_DIM];
__device__ float g_wqr[(size_t)KD*D_DIM];
__device__ float g_wkr[(size_t)KD*D_DIM];
__device__ float g_wvr[(size_t)VD*D_DIM];
__device__ float g_wgr[(size_t)VD*D_DIM];
__device__ float g_g1r[(size_t)GENW*D_DIM];
__device__ float g_wor[(size_t)D_DIM*VD];

__device__ __forceinline__ float siluf(float x) { return x / (1.0f + expf(-x)); }

__device__ __forceinline__ float f2tf32f(float x) {
    uint32_t u;
    asm("cvt.rna.tf32.f32 %0, %1;" : "=r"(u) : "f"(x));
    return __uint_as_float(u);
}
__device__ __forceinline__ uint32_t smem_u32(const void* p) {
    uint32_t a;
    asm("{ .reg .u64 t; cvta.to.shared.u64 t, %1; cvt.u32.u64 %0, t; }" : "=r"(a) : "l"(p));
    return a;
}
__device__ __forceinline__ void cp16s(uint32_t sa, const void* g) {
    asm volatile("cp.async.cg.shared.global [%0], [%1], 16;" :: "r"(sa), "l"(g) : "memory");
}

// ---------------- prep: tf32 round + k-permute (+ weight transpose) ----------------
__global__ __launch_bounds__(256)
void prep_kernel(const float* __restrict__ h,
                 const float* __restrict__ wq, const float* __restrict__ wk,
                 const float* __restrict__ wv, const float* __restrict__ wg,
                 const float* __restrict__ g1, const float* __restrict__ wo,
                 float* __restrict__ hr,
                 float* __restrict__ wqr, float* __restrict__ wkr,
                 float* __restrict__ wvr, float* __restrict__ wgr,
                 float* __restrict__ g1r, float* __restrict__ wor) {
    int b = blockIdx.x;
    if (b < 2048) {
        size_t e0 = ((size_t)b * 256 + threadIdx.x) * 16;
        float4 r0 = *(const float4*)(h + e0);
        float4 r1 = *(const float4*)(h + e0 + 4);
        float4 r2 = *(const float4*)(h + e0 + 8);
        float4 r3 = *(const float4*)(h + e0 + 12);
        float4 o0 = make_float4(f2tf32f(r0.x), f2tf32f(r1.x), f2tf32f(r2.x), f2tf32f(r3.x));
        float4 o1 = make_float4(f2tf32f(r0.y), f2tf32f(r1.y), f2tf32f(r2.y), f2tf32f(r3.y));
        float4 o2 = make_float4(f2tf32f(r0.z), f2tf32f(r1.z), f2tf32f(r2.z), f2tf32f(r3.z));
        float4 o3 = make_float4(f2tf32f(r0.w), f2tf32f(r1.w), f2tf32f(r2.w), f2tf32f(r3.w));
        *(float4*)(hr + e0)      = o0;
        *(float4*)(hr + e0 + 4)  = o1;
        *(float4*)(hr + e0 + 8)  = o2;
        *(float4*)(hr + e0 + 12) = o3;
        return;
    }
    b -= 2048;
    const float* W; float* O; int K, N;
    if (b < 768)                 { W = wq; O = wqr; K = D_DIM; N = KD; }
    else if ((b -= 768) < 768)   { W = wk; O = wkr; K = D_DIM; N = KD; }
    else if ((b -= 768) < 1536)  { W = wv; O = wvr; K = D_DIM; N = VD; }
    else if ((b -= 1536) < 1536) { W = wg; O = wgr; K = D_DIM; N = VD; }
    else if ((b -= 1536) < 128)  { W = g1; O = g1r; K = D_DIM; N = GENW; }
    else                         { b -= 128; W = wo; O = wor; K = VD; N = D_DIM; }
    int ntx = N >> 6;
    int tn = b % ntx, tk = b / ntx;
    int kb = tk * 64, nb = tn * 64;
    __shared__ float tile[64][65];
    int c = threadIdx.x & 63, r0i = threadIdx.x >> 6;
    #pragma unroll
    for (int i = 0; i < 16; i++) {
        int r = r0i + i * 4;
        tile[r][c] = W[(size_t)(kb + r) * N + nb + c];
    }
    __syncthreads();
    int nl = threadIdx.x >> 2, grp = threadIdx.x & 3;
    float* orow = O + (size_t)(nb + nl) * K + kb + grp * 16;
    #pragma unroll
    for (int a = 0; a < 4; a++) {
        float4 o;
        o.x = f2tf32f(tile[grp*16 + a     ][nl]);
        o.y = f2tf32f(tile[grp*16 + a + 4 ][nl]);
        o.z = f2tf32f(tile[grp*16 + a + 8 ][nl]);
        o.w = f2tf32f(tile[grp*16 + a + 12][nl]);
        *(float4*)(orow + a * 4) = o;
    }
}

// ---------------- tf32 GEMM body (permuted operands, LDS.128 frags) ----------------
#define GEMM_SMEM 65536

__device__ __forceinline__ void gemm_body(
    const float* __restrict__ A, const float* __restrict__ B, float* __restrict__ C,
    int K, int Ns, int row0, int col0, int act)
{
    extern __shared__ float sm[];
    const int tid  = threadIdx.x;
    const int warp = tid >> 5, lane = tid & 31;
    const int gid  = lane >> 2, tig = lane & 3;
    const int wm   = warp >> 1, wn = warp & 1;
    const int KT   = K >> 4;
    const uint32_t smb = smem_u32(sm);

    float acc[2][8][4];
    #pragma unroll
    for (int i = 0; i < 2; i++)
        #pragma unroll
        for (int j = 0; j < 8; j++)
            #pragma unroll
            for (int cc = 0; cc < 4; cc++) acc[i][j][cc] = 0.0f;

    const int rA = tid >> 2,        cA = (tid & 3) * 4;
    const float* Abase = A + (size_t)(row0 + rA) * K + cA;
    const float* Bbase = B + (size_t)(col0 + rA) * K + cA;

    auto issue = [&](int kt) {
        if (kt < KT) {
            uint32_t so = smb + (uint32_t)(kt & 3) * 16384u + (uint32_t)(rA * 16 + cA) * 4u;
            int k0 = kt << 4;
            cp16s(so,                 Abase + k0);
            cp16s(so + 4096,          Abase + k0 + (size_t)64 * K);
            cp16s(so + 8192,          Bbase + k0);
            cp16s(so + 8192 + 4096,   Bbase + k0 + (size_t)64 * K);
        }
        asm volatile("cp.async.commit_group;" ::: "memory");
    };

    issue(0); issue(1); issue(2);
    for (int kt = 0; kt < KT; ++kt) {
        asm volatile("cp.async.wait_group 2;" ::: "memory");
        __syncthreads();
        issue(kt + 3);

        const float* As = sm + (kt & 3) * 4096;
        const float* Bs = As + 2048;

        float4 A0[2], A1[2];
        #pragma unroll
        for (int i = 0; i < 2; i++) {
            int m = wm * 32 + i * 16 + gid;
            A0[i] = *(const float4*)(As + m * 16 + tig * 4);
            A1[i] = *(const float4*)(As + (m + 8) * 16 + tig * 4);
        }
        #pragma unroll
        for (int jh = 0; jh < 2; jh++) {
            float4 Bv[4];
            #pragma unroll
            for (int j = 0; j < 4; j++) {
                int n = wn * 64 + (jh * 4 + j) * 8 + gid;
                Bv[j] = *(const float4*)(Bs + n * 16 + tig * 4);
            }
            #pragma unroll
            for (int i = 0; i < 2; i++)
                #pragma unroll
                for (int j = 0; j < 4; j++) {
                    float* ac = acc[i][jh * 4 + j];
                    asm volatile(
                        "mma.sync.aligned.m16n8k8.row.col.f32.tf32.tf32.f32 "
                        "{%0,%1,%2,%3}, {%4,%5,%6,%7}, {%8,%9}, {%0,%1,%2,%3};"
                        : "+f"(ac[0]), "+f"(ac[1]), "+f"(ac[2]), "+f"(ac[3])
                        : "r"(__float_as_uint(A0[i].x)), "r"(__float_as_uint(A1[i].x)),
                          "r"(__float_as_uint(A0[i].y)), "r"(__float_as_uint(A1[i].y)),
                          "r"(__float_as_uint(Bv[j].x)), "r"(__float_as_uint(Bv[j].y)));
                    asm volatile(
                        "mma.sync.aligned.m16n8k8.row.col.f32.tf32.tf32.f32 "
                        "{%0,%1,%2,%3}, {%4,%5,%6,%7}, {%8,%9}, {%0,%1,%2,%3};"
                        : "+f"(ac[0]), "+f"(ac[1]), "+f"(ac[2]), "+f"(ac[3])
                        : "r"(__float_as_uint(A0[i].z)), "r"(__float_as_uint(A1[i].z)),
                          "r"(__float_as_uint(A0[i].w)), "r"(__float_as_uint(A1[i].w)),
                          "r"(__float_as_uint(Bv[j].z)), "r"(__float_as_uint(Bv[j].w)));
                }
        }
    }

    #pragma unroll
    for (int i = 0; i < 2; ++i) {
        int row = row0 + wm * 32 + i * 16 + gid;
        #pragma unroll
        for (int j = 0; j < 8; ++j) {
            int col = col0 + wn * 64 + j * 8 + 2 * tig;
            float v0 = acc[i][j][0], v1 = acc[i][j][1];
            float v2 = acc[i][j][2], v3 = acc[i][j][3];
            if (act) { v0 = siluf(v0); v1 = siluf(v1); v2 = siluf(v2); v3 = siluf(v3); }
            *(float2*)(C + (size_t)row * Ns + col)       = make_float2(v0, v1);
            *(float2*)(C + (size_t)(row + 8) * Ns + col) = make_float2(v2, v3);
        }
    }
}

__global__ __launch_bounds__(256, 2)
void proj_gemm_kernel(const float* __restrict__ hR,
                      const float* __restrict__ WqR, const float* __restrict__ WkR,
                      const float* __restrict__ WvR, const float* __restrict__ WgR,
                      const float* __restrict__ g1R,
                      float* __restrict__ q, float* __restrict__ k,
                      float* __restrict__ x, float* __restrict__ g,
                      float* __restrict__ d1) {
    const int by = blockIdx.y;
    const float* B; float* C; int Ns, col0, act;
    if (by < 12)      { B = WqR; C = q;  Ns = KD;   col0 = by * 128;        act = 1; }
    else if (by < 24) { B = WkR; C = k;  Ns = KD;   col0 = (by - 12) * 128; act = 1; }
    else if (by < 48) { B = WvR; C = x;  Ns = VD;   col0 = (by - 24) * 128; act = 0; }
    else if (by < 72) { B = WgR; C = g;  Ns = VD;   col0 = (by - 48) * 128; act = 0; }
    else              { B = g1R; C = d1; Ns = GENW; col0 = (by - 72) * 128; act = 1; }
    gemm_body(hR, B, C, D_DIM, Ns, blockIdx.x * 128, col0, act);
}

__global__ __launch_bounds__(256, 2)
void wo_gemm_kernel(const float* __restrict__ yR, const float* __restrict__ WoR,
                    float* __restrict__ out) {
    gemm_body(yR, WoR, out, VD, D_DIM, blockIdx.x * 128, blockIdx.y * 128, 0);
}

// ---------------- dyn = dyn1[T,256] @ gen_w2[256,4] (warp per token) ----------------
__global__ __launch_bounds__(256)
void dyn2_kernel(const float* __restrict__ dyn1, const float* __restrict__ w2,
                 float* __restrict__ dyn) {
    int t    = blockIdx.x * 8 + (threadIdx.x >> 5);
    int lane = threadIdx.x & 31;
    const float* r = dyn1 + (size_t)t * GENW;
    float a0 = 0.f, a1 = 0.f, a2 = 0.f, a3 = 0.f;
    #pragma unroll
    for (int i = 0; i < 8; i++) {
        int d = lane + 32*i;
        float v = r[d];
        const float* w = w2 + d*4;
        a0 += v*w[0]; a1 += v*w[1]; a2 += v*w[2]; a3 += v*w[3];
    }
    #pragma unroll
    for (int off = 16; off; off >>= 1) {
        a0 += __shfl_xor_sync(0xffffffffu, a0, off);
        a1 += __shfl_xor_sync(0xffffffffu, a1, off);
        a2 += __shfl_xor_sync(0xffffffffu, a2, off);
        a3 += __shfl_xor_sync(0xffffffffu, a3, off);
    }
    if (lane == 0) {
        dyn[t*4+0] = a0; dyn[t*4+1] = a1; dyn[t*4+2] = a2; dyn[t*4+3] = a3;
    }
}

// ---------------- betag -> scal.{x,y} ----------------
__global__ __launch_bounds__(256)
void betag_kernel(const float* __restrict__ h, const float* __restrict__ Wb,
                  const float* __restrict__ Wa, const float* __restrict__ A_log,
                  const float* __restrict__ dt_bias, float* __restrict__ scal) {
    int t = blockIdx.x;
    const float* hr = h + (size_t)t * D_DIM;
    float acc[12];
    #pragma unroll
    for (int j = 0; j < 12; j++) acc[j] = 0.f;
    for (int d = threadIdx.x; d < D_DIM; d += 256) {
        float hv = hr[d];
        const float* wb = Wb + d*6;
        const float* wa = Wa + d*6;
        #pragma unroll
        for (int j = 0; j < 6; j++) {
            acc[j]   += hv * wb[j];
            acc[6+j] += hv * wa[j];
        }
    }
    #pragma unroll
    for (int j = 0; j < 12; j++)
        #pragma unroll
        for (int off = 16; off; off >>= 1)
            acc[j] += __shfl_xor_sync(0xffffffffu, acc[j], off);

    __shared__ float red[8][12];
    int w = threadIdx.x >> 5, lane = threadIdx.x & 31;
    if (lane == 0) {
        #pragma unroll
        for (int j = 0; j < 12; j++) red[w][j] = acc[j];
    }
    __syncthreads();
    if (threadIdx.x < 12) {
        float s = 0.f;
        #pragma unroll
        for (int i = 0; i < 8; i++) s += red[i][threadIdx.x];
        int j = threadIdx.x;
        if (j < 6) {
            scal[(size_t)(t*6 + j) * 4 + 1] = 1.0f / (1.0f + expf(-s));     // beta
        } else {
            int hh = j - 6;
            float xx = s + dt_bias[hh];
            float sp = (xx > 20.0f) ? xx : log1pf(expf(xx));
            scal[(size_t)(t*6 + hh) * 4 + 0] = expf(-expf(A_log[hh]) * sp); // eg
        }
    }
}

// ---------------- dynamic short conv + silu ----------------
__global__ __launch_bounds__(256)
void conv_silu_kernel(const float* __restrict__ x, const float* __restrict__ dyn,
                      const float* __restrict__ cw, float* __restrict__ v) {
    int idx = blockIdx.x * 256 + threadIdx.x;
    int t = idx / (VD/4);
    if (t >= T_LEN) return;
    int c = (idx - t * (VD/4)) * 4;
    float d[4];
    #pragma unroll
    for (int j = 0; j < 4; j++) d[j] = dyn[t*4 + j];
    float a0 = 0.f, a1 = 0.f, a2 = 0.f, a3 = 0.f;
    #pragma unroll
    for (int j = 0; j < 4; j++) {
        int tt = t + j - 3;
        if (tt >= 0) {
            float4 xv = *(const float4*)(x + (size_t)tt * VD + c);
            a0 += (cw[(c+0)*4 + j] + d[j]) * xv.x;
            a1 += (cw[(c+1)*4 + j] + d[j]) * xv.y;
            a2 += (cw[(c+2)*4 + j] + d[j]) * xv.z;
            a3 += (cw[(c+3)*4 + j] + d[j]) * xv.w;
        }
    }
    float4 r;
    r.x = siluf(a0); r.y = siluf(a1); r.z = siluf(a2); r.w = siluf(a3);
    *(float4*)(v + (size_t)t * VD + c) = r;
}

// ---------------- fused l2norm + qk + pair cross products (warp per (pair,head)) ---
// One butterfly phase for 8 raw dots: |q0|²,|k0|²,|q1|²,|k1|²,q0·k0,q1·k1,k1·k0,q1·k0.
// Writes normalized q,k (scale folded into q) and scal.z (qk) / scal.w (kk|qx).
__global__ __launch_bounds__(256)
void l2qkx_kernel(float* __restrict__ q, float* __restrict__ k,
                  float* __restrict__ scal) {
    int wg   = blockIdx.x * 8 + (threadIdx.x >> 5);   // 0..12287 = pair*6 + head
    int lane = threadIdx.x & 31;
    int pair = wg / 6, head = wg - pair * 6;
    int t = pair * 2;
    float* q0r = q + ((size_t)t * 6 + head) * DKDIM;
    float* k0r = k + ((size_t)t * 6 + head) * DKDIM;
    float* q1r = q + ((size_t)(t + 1) * 6 + head) * DKDIM;
    float* k1r = k + ((size_t)(t + 1) * 6 + head) * DKDIM;

    float xq0[8], xk0[8], xq1[8], xk1[8];
    float sq0=0.f, sk0=0.f, sq1=0.f, sk1=0.f, sx0=0.f, sx1=0.f, kkr=0.f, qxr=0.f;
    #pragma unroll
    for (int i = 0; i < 8; i++) {
        int d = lane + 32*i;
        xq0[i] = q0r[d]; xk0[i] = k0r[d];
        xq1[i] = q1r[d]; xk1[i] = k1r[d];
        sq0 += xq0[i]*xq0[i]; sk0 += xk0[i]*xk0[i];
        sq1 += xq1[i]*xq1[i]; sk1 += xk1[i]*xk1[i];
        sx0 += xq0[i]*xk0[i]; sx1 += xq1[i]*xk1[i];
        kkr += xk1[i]*xk0[i]; qxr += xq1[i]*xk0[i];
    }
    #pragma unroll
    for (int off = 16; off; off >>= 1) {
        sq0 += __shfl_xor_sync(0xffffffffu, sq0, off);
        sk0 += __shfl_xor_sync(0xffffffffu, sk0, off);
        sq1 += __shfl_xor_sync(0xffffffffu, sq1, off);
        sk1 += __shfl_xor_sync(0xffffffffu, sk1, off);
        sx0 += __shfl_xor_sync(0xffffffffu, sx0, off);
        sx1 += __shfl_xor_sync(0xffffffffu, sx1, off);
        kkr += __shfl_xor_sync(0xffffffffu, kkr, off);
        qxr += __shfl_xor_sync(0xffffffffu, qxr, off);
    }
    float rq0 = rsqrtf(sq0 + 1e-6f) * 0.0625f;   // fold DK^-0.5 into q
    float rk0 = rsqrtf(sk0 + 1e-6f);
    float rq1 = rsqrtf(sq1 + 1e-6f) * 0.0625f;
    float rk1 = rsqrtf(sk1 + 1e-6f);
    #pragma unroll
    for (int i = 0; i < 8; i++) {
        int d = lane + 32*i;
        q0r[d] = xq0[i] * rq0;  k0r[d] = xk0[i] * rk0;
        q1r[d] = xq1[i] * rq1;  k1r[d] = xk1[i] * rk1;
    }
    if (lane == 0) {
        scal[((size_t)t * 6 + head) * 4 + 2]       = sx0 * rq0 * rk0;  // qk even
        scal[((size_t)t * 6 + head) * 4 + 3]       = kkr * rk1 * rk0;  // kk
        scal[((size_t)(t + 1) * 6 + head) * 4 + 2] = sx1 * rq1 * rk1;  // qk odd
        scal[((size_t)(t + 1) * 6 + head) * 4 + 3] = qxr * rq1 * rk0;  // qx
    }
}

// ---------------- paired gated delta-rule scan (R14 WIN config, unchanged) --------
__global__ __launch_bounds__(128)
void scan_kernel(const float* __restrict__ q, const float* __restrict__ k,
                 const float* __restrict__ v, const float4* __restrict__ scal,
                 float* __restrict__ o) {
    const int warpg = blockIdx.x * 4 + (threadIdx.x >> 5);
    const int c0    = warpg * 2;
    const int head  = c0 >> 9;
    const int lane  = threadIdx.x & 31;

    const float* qb = q + head * DKDIM + lane;
    const float* kb = k + head * DKDIM + lane;

    float s0[8], s1[8];
    #pragma unroll
    for (int i = 0; i < 8; i++) { s0[i] = 0.f; s1[i] = 0.f; }

    float qa0[8], ka0[8], qa1[8], ka1[8]; float2 va0, va1; float4 sa0, sa1;
    float qb0[8], kb0[8], qb1[8], kb1[8]; float2 vb0, vb1; float4 sb0, sb1;

    #define PAIR_LOAD(t, Q0, K0, Q1, K1, V0, V1, S0_, S1_) do {        \
        size_t _o0 = (size_t)(t) * KD, _o1 = (size_t)((t)+1) * KD;     \
        _Pragma("unroll")                                              \
        for (int _i = 0; _i < 8; _i++) {                               \
            Q0[_i] = qb[_o0 + 32*_i];  K0[_i] = kb[_o0 + 32*_i];       \
            Q1[_i] = qb[_o1 + 32*_i];  K1[_i] = kb[_o1 + 32*_i];       \
        }                                                              \
        V0 = *(const float2*)(v + (size_t)(t) * VD + c0);              \
        V1 = *(const float2*)(v + (size_t)((t)+1) * VD + c0);          \
        S0_ = scal[(t)*6 + head];                                      \
        S1_ = scal[((t)+1)*6 + head];                                  \
    } while (0)

    #define PAIR_STEP(t, Q0, K0, Q1, K1, V0, V1, S0_, S1_) do {        \
        float E1 = S0_.x, b0c = S0_.y, qk0 = S0_.z, kkc = S0_.w;       \
        float E2 = S1_.x, b1c = S1_.y, qk1 = S1_.z, qxc = S1_.w;       \
        float E12 = E1 * E2;                                           \
        float rA0=0.f,rB0=0.f,rC0=0.f,rD0=0.f;                         \
        float rA1=0.f,rB1=0.f,rC1=0.f,rD1=0.f;                         \
        _Pragma("unroll")                                              \
        for (int _i = 0; _i < 8; _i++) {                               \
            float t0 = s0[_i], t1 = s1[_i];                            \
            rA0 += K0[_i]*t0; rA1 += K0[_i]*t1;                        \
            rB0 += Q0[_i]*t0; rB1 += Q0[_i]*t1;                        \
            rC0 += K1[_i]*t0; rC1 += K1[_i]*t1;                        \
            rD0 += Q1[_i]*t0; rD1 += Q1[_i]*t1;                        \
        }                                                              \
        _Pragma("unroll")                                              \
        for (int _off = 16; _off; _off >>= 1) {                        \
            rA0 += __shfl_xor_sync(0xffffffffu, rA0, _off);            \
            rA1 += __shfl_xor_sync(0xffffffffu, rA1, _off);            \
            rB0 += __shfl_xor_sync(0xffffffffu, rB0, _off);            \
            rB1 += __shfl_xor_sync(0xffffffffu, rB1, _off);            \
            rC0 += __shfl_xor_sync(0xffffffffu, rC0, _off);            \
            rC1 += __shfl_xor_sync(0xffffffffu, rC1, _off);            \
            rD0 += __shfl_xor_sync(0xffffffffu, rD0, _off);            \
            rD1 += __shfl_xor_sync(0xffffffffu, rD1, _off);            \
        }                                                              \
        float dv0_0 = (V0.x - E1*rA0) * b0c;                           \
        float d1_0  = E12*rC0 + E2*kkc*dv0_0;                          \
        float dv1_0 = (V1.x - d1_0) * b1c;                             \
        float dv0_1 = (V0.y - E1*rA1) * b0c;                           \
        float d1_1  = E12*rC1 + E2*kkc*dv0_1;                          \
        float dv1_1 = (V1.y - d1_1) * b1c;                             \
        if (lane == 0) {                                               \
            *(float2*)(o + (size_t)(t) * VD + c0) = make_float2(       \
                E1*rB0 + qk0*dv0_0, E1*rB1 + qk0*dv0_1);               \
            *(float2*)(o + (size_t)((t)+1) * VD + c0) = make_float2(   \
                E12*rD0 + E2*qxc*dv0_0 + qk1*dv1_0,                    \
                E12*rD1 + E2*qxc*dv0_1 + qk1*dv1_1);                   \
        }                                                              \
        float e2d0 = E2 * dv0_0, e2d1 = E2 * dv0_1;                    \
        _Pragma("unroll")                                              \
        for (int _i = 0; _i < 8; _i++) {                               \
            s0[_i] = E12*s0[_i] + e2d0*K0[_i] + dv1_0*K1[_i];          \
            s1[_i] = E12*s1[_i] + e2d1*K0[_i] + dv1_1*K1[_i];          \
        }                                                              \
    } while (0)

    PAIR_LOAD(0, qa0, ka0, qa1, ka1, va0, va1, sa0, sa1);
    for (int t = 0; t < T_LEN; t += 4) {
        PAIR_LOAD(t + 2, qb0, kb0, qb1, kb1, vb0, vb1, sb0, sb1);
        PAIR_STEP(t, qa0, ka0, qa1, ka1, va0, va1, sa0, sa1);
        if (t + 4 < T_LEN) PAIR_LOAD(t + 4, qa0, ka0, qa1, ka1, va0, va1, sa0, sa1);
        PAIR_STEP(t + 2, qb0, kb0, qb1, kb1, vb0, vb1, sb0, sb1);
    }
    #undef PAIR_LOAD
    #undef PAIR_STEP
}

// ---------------- gated RMSNorm -> tf32-rounded, k-permuted y ----------------
__global__ __launch_bounds__(128)
void rmsnorm_gate_kernel(const float* __restrict__ o, const float* __restrict__ gate,
                         const float* __restrict__ nw, float* __restrict__ y) {
    int row = blockIdx.x;                  // t*6 + h
    int tid = threadIdx.x;
    size_t base = (size_t)(row / 6) * VD + (size_t)(row % 6) * DVDIM;
    int g = tid >> 2, a = tid & 3;

    float ov[4], gv[4], nv[4];
    float ss = 0.f;
    #pragma unroll
    for (int i = 0; i < 4; i++) {
        int c = g * 16 + a + 4 * i;
        ov[i] = o[base + c];
        gv[i] = gate[base + c];
        nv[i] = nw[c];
        ss += ov[i] * ov[i];
    }
    #pragma unroll
    for (int off = 16; off; off >>= 1) ss += __shfl_xor_sync(0xffffffffu, ss, off);
    __shared__ float red[4];
    int w = tid >> 5, lane = tid & 31;
    if (lane == 0) red[w] = ss;
    __syncthreads();
    float tot = red[0] + red[1] + red[2] + red[3];
    float rms = rsqrtf(tot * (1.0f / (float)DVDIM) + 1e-5f);

    float4 r;
    r.x = f2tf32f(ov[0] * rms * nv[0] * siluf(gv[0]));
    r.y = f2tf32f(ov[1] * rms * nv[1] * siluf(gv[1]));
    r.z = f2tf32f(ov[2] * rms * nv[2] * siluf(gv[2]));
    r.w = f2tf32f(ov[3] * rms * nv[3] * siluf(gv[3]));
    *(float4*)(y + base + g * 16 + 4 * a) = r;
}

// ---------------- launch ----------------
extern "C" void kernel_launch(void* const* d_in, const int* in_sizes, int n_in,
                              void* d_out, int out_size) {
    const float* h       = (const float*)d_in[0];
    const float* Wq      = (const float*)d_in[1];
    const float* Wk      = (const float*)d_in[2];
    const float* Wv      = (const float*)d_in[3];
    const float* Wb      = (const float*)d_in[4];
    const float* Wa      = (const float*)d_in[5];
    const float* Wg      = (const float*)d_in[6];
    const float* Wo      = (const float*)d_in[7];
    const float* A_log   = (const float*)d_in[8];
    const float* dt_bias = (const float*)d_in[9];
    const float* conv_w  = (const float*)d_in[10];
    const float* gen_w1  = (const float*)d_in[11];
    const float* gen_w2  = (const float*)d_in[12];
    const float* norm_w  = (const float*)d_in[13];
    float* out = (float*)d_out;

    float *pq, *pk, *px, *pv, *pd1, *pd, *pgate, *po;
    float4* pscal;
    float *phr, *pwqr, *pwkr, *pwvr, *pwgr, *pg1r, *pwor;
    cudaGetSymbolAddress((void**)&pq,    g_q);
    cudaGetSymbolAddress((void**)&pk,    g_k);
    cudaGetSymbolAddress((void**)&px,    g_x);
    cudaGetSymbolAddress((void**)&pv,    g_v);
    cudaGetSymbolAddress((void**)&pd1,   g_dyn1);
    cudaGetSymbolAddress((void**)&pd,    g_dyn);
    cudaGetSymbolAddress((void**)&pgate, g_gate);
    cudaGetSymbolAddress((void**)&po,    g_o);
    cudaGetSymbolAddress((void**)&pscal, g_scal);
    cudaGetSymbolAddress((void**)&phr,   g_hr);
    cudaGetSymbolAddress((void**)&pwqr,  g_wqr);
    cudaGetSymbolAddress((void**)&pwkr,  g_wkr);
    cudaGetSymbolAddress((void**)&pwvr,  g_wvr);
    cudaGetSymbolAddress((void**)&pwgr,  g_wgr);
    cudaGetSymbolAddress((void**)&pg1r,  g_g1r);
    cudaGetSymbolAddress((void**)&pwor,  g_wor);

    cudaFuncSetAttribute(proj_gemm_kernel, cudaFuncAttributeMaxDynamicSharedMemorySize, GEMM_SMEM);
    cudaFuncSetAttribute(wo_gemm_kernel,   cudaFuncAttributeMaxDynamicSharedMemorySize, GEMM_SMEM);

    // (0) round + permute h, transpose + round + permute weights
    prep_kernel<<<8320, 256>>>(h, Wq, Wk, Wv, Wg, gen_w1, Wo,
                               phr, pwqr, pwkr, pwvr, pwgr, pg1r, pwor);

    // (1) fused projections q|k|x|gate|dyn1 (74 x 32 tiles)
    proj_gemm_kernel<<<dim3(T_LEN/128, 74), 256, GEMM_SMEM>>>(
        phr, pwqr, pwkr, pwvr, pwgr, pg1r, pq, pk, px, pgate, pd1);

    // (2..5) elementwise stages
    dyn2_kernel<<<T_LEN/8, 256>>>(pd1, gen_w2, pd);
    betag_kernel<<<T_LEN, 256>>>(h, Wb, Wa, A_log, dt_bias, (float*)pscal);
    conv_silu_kernel<<<(T_LEN*(VD/4))/256, 256>>>(px, pd, conv_w, pv);
    l2qkx_kernel<<<(T_LEN/2*H_N)/8, 256>>>(pq, pk, (float*)pscal);

    // (6) paired two-step scan (R14 WIN)
    scan_kernel<<<384, 128>>>(pq, pk, pv, pscal, po);

    // (7) gated RMSNorm -> permuted tf32 y (reuses g_x)
    rmsnorm_gate_kernel<<<T_LEN*H_N, 128>>>(po, pgate, norm_w, px);

    // (8) out = y @ Wo
    wo_gemm_kernel<<<dim3(T_LEN/128, D_DIM/128), 256, GEMM_SMEM>>>(px, pwor, out);
}